// round 15
// baseline (speedup 1.0000x reference)
#include <cuda_runtime.h>
#include <math.h>
#include <stdint.h>

#define C_EMBED 768
#define NH 12
#define HD 64
#define BATCH 2
#define SEQ 4096
#define MROWS (BATCH*SEQ)        // 8192
#define C3 (3*C_EMBED)           // 2304

// Scratch (no allocations allowed) — tf32 bit buffers
__device__ __align__(16) uint32_t g_qkv[(size_t)MROWS * C3];          // 75.5 MB (V third unused)
__device__ __align__(16) uint32_t g_vt[(size_t)MROWS * C_EMBED];      // 25 MB  V^T [b][h][d][t]
__device__ __align__(16) uint32_t g_att[(size_t)MROWS * C_EMBED];     // 25 MB
__device__ __align__(16) uint32_t g_xt[(size_t)MROWS * C_EMBED];      // 25 MB
__device__ __align__(16) uint32_t g_wqkvt[(size_t)C_EMBED * C3];      // 7 MB  W_qkv^T [N][K]
__device__ __align__(16) uint32_t g_wprojt[(size_t)C_EMBED * C_EMBED];// 2.4 MB W_proj^T [N][K]

// ---------------------------------------------------------------------------
// helpers
// ---------------------------------------------------------------------------
__device__ __forceinline__ uint32_t f2tf32(float v) {
    uint32_t t;
    asm("cvt.rna.tf32.f32 %0, %1;" : "=r"(t) : "f"(v));
    return t;
}

__device__ __forceinline__ float ex2(float x) {
    float r;
    asm("ex2.approx.f32 %0, %1;" : "=f"(r) : "f"(x));
    return r;
}

__device__ __forceinline__ void mma16n8k8(float* d, const uint32_t* a, const uint32_t* b) {
    asm volatile(
        "mma.sync.aligned.m16n8k8.row.col.f32.tf32.tf32.f32 "
        "{%0,%1,%2,%3}, {%4,%5,%6,%7}, {%8,%9}, {%0,%1,%2,%3};"
        : "+f"(d[0]), "+f"(d[1]), "+f"(d[2]), "+f"(d[3])
        : "r"(a[0]), "r"(a[1]), "r"(a[2]), "r"(a[3]), "r"(b[0]), "r"(b[1]));
}

// one instruction -> 4 fragment registers (8x4 tf32 blocks)
__device__ __forceinline__ void ldmx4(uint32_t* r, uint32_t a) {
    asm volatile("ldmatrix.sync.aligned.m8n8.x4.shared.b16 {%0,%1,%2,%3}, [%4];"
                 : "=r"(r[0]), "=r"(r[1]), "=r"(r[2]), "=r"(r[3]) : "r"(a));
}

__device__ __forceinline__ uint32_t smem_u32(const void* p) {
    uint32_t a;
    asm("{ .reg .u64 t; cvta.to.shared.u64 t, %1; cvt.u32.u64 %0, t; }"
        : "=r"(a) : "l"(p));
    return a;
}

// L1-bypass async copy: fills smem without allocating L1 lines (.cg, 16B only).
__device__ __forceinline__ void cp_async16(uint32_t saddr, const void* gptr) {
    asm volatile("cp.async.cg.shared.global [%0], [%1], 16;"
                 :: "r"(saddr), "l"(gptr));
}
__device__ __forceinline__ void cp_commit() {
    asm volatile("cp.async.commit_group;" ::: "memory");
}
__device__ __forceinline__ void cp_wait1() {
    asm volatile("cp.async.wait_group 1;" ::: "memory");
}
__device__ __forceinline__ void cp_wait0() {
    asm volatile("cp.async.wait_group 0;" ::: "memory");
}

// ---------------------------------------------------------------------------
// elementwise fp32 -> tf32-bits pre-pass (activations)
// ---------------------------------------------------------------------------
__global__ void __launch_bounds__(256) cvt_tf32_kernel(
    const float4* __restrict__ in, uint4* __restrict__ out, int n4)
{
    int i = blockIdx.x * blockDim.x + threadIdx.x;
    if (i < n4) {
        float4 v = in[i];
        uint4 t;
        t.x = f2tf32(v.x); t.y = f2tf32(v.y);
        t.z = f2tf32(v.z); t.w = f2tf32(v.w);
        out[i] = t;
    }
}

// fused cvt + transpose for weights: in[K][N] fp32 -> out[N][K] tf32 bits
__global__ void __launch_bounds__(256) cvt_transpose_kernel(
    const float* __restrict__ in, uint32_t* __restrict__ out, int K, int N)
{
    __shared__ uint32_t t[32][33];
    const int n0 = blockIdx.x * 32;
    const int k0 = blockIdx.y * 32;
    const int tx = threadIdx.x;
    const int ty = threadIdx.y;
#pragma unroll
    for (int i = 0; i < 32; i += 8)
        t[ty + i][tx] = f2tf32(in[(size_t)(k0 + ty + i) * N + n0 + tx]);
    __syncthreads();
#pragma unroll
    for (int i = 0; i < 32; i += 8)
        out[(size_t)(n0 + ty + i) * K + k0 + tx] = t[tx][ty + i];
}

// ===========================================================================
// tf32-bit mma GEMM (verified R13/R14 structure, cp.async now .cg).
// MODE 1 Q-scale folds 0.125*log2(e) for exp2-domain softmax.
// ===========================================================================
#define G_AW 36
#define G_ABUF (128 * G_AW)
#define G_STG (2 * G_ABUF)
#define GEMM_SMEM_BYTES (2 * G_STG * 4)   // 73728

#define QSCALE_LOG2E 0.1803368867f        // 0.125 * log2(e)

template<int MODE>
__global__ void __launch_bounds__(256, 2) gemm_tf32_kernel(
    const uint32_t* __restrict__ A, const uint32_t* __restrict__ Bt,
    const float* __restrict__ bias, float* __restrict__ Cm,
    uint32_t* __restrict__ Vt,
    int M, int N, int K)
{
    extern __shared__ uint32_t gsm[];
    const uint32_t sb = smem_u32(gsm);

    const int tid = threadIdx.x;
    const int w   = tid >> 5;
    const int L   = tid & 31;
    const int gid = L >> 2;
    const int tig = L & 3;
    const int row0 = blockIdx.y * 128;
    const int col0 = blockIdx.x * 128;
    const int m0w = (w & 1) * 64;
    const int n0w = (w >> 1) * 32;
    const int nk = K >> 5;

    const int am = L >> 3;
    const int arow_off = ((am & 1) << 3) + (L & 7);
    const int acol_off = (am >> 1) << 2;
    const int bm = L >> 3;
    const int brow_off = ((bm >> 1) << 3) + (L & 7);
    const int bcol_off = (bm & 1) << 2;

    float acc[4][4][4];
#pragma unroll
    for (int mt = 0; mt < 4; mt++)
#pragma unroll
        for (int nt = 0; nt < 4; nt++)
#pragma unroll
            for (int e = 0; e < 4; e++) acc[mt][nt][e] = 0.f;

    auto issue = [&](int t, int bf) {
        const int kb = t * 32;
        const uint32_t base = sb + (uint32_t)(bf * G_STG * 4);
#pragma unroll
        for (int u = 0; u < 4; u++) {
            int fid = u * 256 + tid;
            int r   = fid >> 3;
            int c4  = fid & 7;
            cp_async16(base + (uint32_t)((r * G_AW + c4 * 4) * 4),
                       &A[(size_t)(row0 + r) * K + kb + c4 * 4]);
        }
#pragma unroll
        for (int u = 0; u < 4; u++) {
            int fid = u * 256 + tid;
            int r   = fid >> 3;
            int c4  = fid & 7;
            cp_async16(base + (uint32_t)((G_ABUF + r * G_AW + c4 * 4) * 4),
                       &Bt[(size_t)(col0 + r) * K + kb + c4 * 4]);
        }
    };

    issue(0, 0);
    cp_commit();

    for (int t = 0; t < nk; t++) {
        const int bf = t & 1;
        if (t + 1 < nk) { issue(t + 1, bf ^ 1); cp_commit(); cp_wait1(); }
        else            { cp_wait0(); }
        __syncthreads();

        const uint32_t sbA = sb + (uint32_t)(bf * G_STG * 4);
        const uint32_t sbB = sbA + (uint32_t)(G_ABUF * 4);

#pragma unroll
        for (int ks = 0; ks < 4; ks++) {
            const int k0 = ks * 8;
            uint32_t af[4][4];
#pragma unroll
            for (int mt = 0; mt < 4; mt++) {
                ldmx4(af[mt], sbA + (uint32_t)(((m0w + mt * 16 + arow_off) * G_AW
                                                + k0 + acol_off) * 4));
            }
            uint32_t bfr[4][2];
#pragma unroll
            for (int ntp = 0; ntp < 2; ntp++) {
                uint32_t bt4[4];
                ldmx4(bt4, sbB + (uint32_t)(((n0w + ntp * 16 + brow_off) * G_AW
                                             + k0 + bcol_off) * 4));
                bfr[2 * ntp][0]     = bt4[0];
                bfr[2 * ntp][1]     = bt4[1];
                bfr[2 * ntp + 1][0] = bt4[2];
                bfr[2 * ntp + 1][1] = bt4[3];
            }
#pragma unroll
            for (int mt = 0; mt < 4; mt++)
#pragma unroll
                for (int nt = 0; nt < 4; nt++)
                    mma16n8k8(acc[mt][nt], af[mt], bfr[nt]);
        }
        __syncthreads();
    }

    // epilogue
#pragma unroll
    for (int mt = 0; mt < 4; mt++) {
        const int r = row0 + m0w + mt * 16 + gid;
#pragma unroll
        for (int nt = 0; nt < 4; nt++) {
            const int c = col0 + n0w + nt * 8 + 2 * tig;
            const float b0 = bias[c], b1 = bias[c + 1];
            if (MODE == 0) {
                float2 v0 = make_float2(acc[mt][nt][0] + b0, acc[mt][nt][1] + b1);
                *(float2*)&Cm[(size_t)r * N + c] = v0;
                float2 v1 = make_float2(acc[mt][nt][2] + b0, acc[mt][nt][3] + b1);
                *(float2*)&Cm[(size_t)(r + 8) * N + c] = v1;
            } else {
                uint2 v0, v1;
                if (c < 2 * C_EMBED) {
                    const float sc = (c < C_EMBED) ? QSCALE_LOG2E : 1.0f;
                    v0.x = f2tf32((acc[mt][nt][0] + b0) * sc);
                    v0.y = f2tf32((acc[mt][nt][1] + b1) * sc);
                    v1.x = f2tf32((acc[mt][nt][2] + b0) * sc);
                    v1.y = f2tf32((acc[mt][nt][3] + b1) * sc);
                    uint32_t* Co = (uint32_t*)Cm;
                    *(uint2*)&Co[(size_t)r * N + c] = v0;
                    *(uint2*)&Co[(size_t)(r + 8) * N + c] = v1;
                } else {
                    // V block -> transposed store Vt[b][h][d][t]
                    v0.x = f2tf32(acc[mt][nt][0] + b0);
                    v0.y = f2tf32(acc[mt][nt][1] + b1);
                    v1.x = f2tf32(acc[mt][nt][2] + b0);
                    v1.y = f2tf32(acc[mt][nt][3] + b1);
                    const int hd = c - 2 * C_EMBED;
                    const int hh = hd >> 6;
                    const int d  = hd & 63;
                    const int bb = r >> 12;
                    const int tt = r & 4095;
                    const size_t base = ((size_t)(bb * NH + hh) * HD + d) * SEQ + tt;
                    Vt[base]           = v0.x;
                    Vt[base + SEQ]     = v0.y;
                    Vt[base + 8]       = v1.x;
                    Vt[base + SEQ + 8] = v1.y;
                }
            }
        }
    }
}

// ===========================================================================
// tf32-bit mma flash attention (causal), exp2-domain softmax, l via P@ones,
// K/V cp.async now .cg (L1 bypass). Verified R14 structure otherwise.
// ===========================================================================
#define A_KW 68
#define A_KBUF (64 * A_KW)
#define A_VBUF (64 * A_KW)
#define A_VOFF (2 * A_KBUF)
#define A_POFF (A_VOFF + 2 * A_VBUF)
#define ATTN_SMEM_BYTES ((A_POFF + 128 * 68) * 4)   // 104448

__global__ void __launch_bounds__(256) attn_tc_kernel(
    const uint32_t* __restrict__ qkv, const uint32_t* __restrict__ vt,
    uint32_t* __restrict__ attout)
{
    extern __shared__ uint32_t asm_[];
    const uint32_t sb = smem_u32(asm_);
    uint32_t* Ps = asm_ + A_POFF;
    const uint32_t sbP = sb + (uint32_t)(A_POFF * 4);

    const int qt  = (int)gridDim.x - 1 - (int)blockIdx.x;   // largest-first
    const int h   = blockIdx.y;
    const int b   = blockIdx.z;
    const int tid = threadIdx.x;
    const int w   = tid >> 5;
    const int L   = tid & 31;
    const int gid = L >> 2;
    const int tig = L & 3;
    const int wrow = w * 16;

    const int km = L >> 3;
    const int krow_off = ((km >> 1) << 3) + (L & 7);
    const int kcol_off = (km & 1) << 2;
    const int pm = L >> 3;
    const int prow_off = ((pm & 1) << 3) + (L & 7);
    const int pcol_off = (pm >> 1) << 2;

    const uint32_t* qbase = qkv + (size_t)b * SEQ * C3 + h * HD;
    const uint32_t* kbase = qbase + C_EMBED;
    const uint32_t* vtb   = vt + (size_t)(b * NH + h) * HD * SEQ;

    // ones B-fragment for row-sum mma (tf32 bits of 1.0f)
    const uint32_t bones[2] = { 0x3F800000u, 0x3F800000u };

    // ---- Q fragments ----
    uint32_t qf[8][4];
    {
        const uint32_t* qr0 = qbase + (size_t)(qt * 128 + wrow + gid) * C3;
        const uint32_t* qr1 = qr0 + 8 * C3;
#pragma unroll
        for (int ks = 0; ks < 8; ks++) {
            const int c = 8 * ks + tig;
            qf[ks][0] = qr0[c];
            qf[ks][1] = qr1[c];
            qf[ks][2] = qr0[c + 4];
            qf[ks][3] = qr1[c + 4];
        }
    }

    float o[8][4];
#pragma unroll
    for (int nt = 0; nt < 8; nt++)
#pragma unroll
        for (int e = 0; e < 4; e++) o[nt][e] = 0.f;
    float m0 = -1e30f, m1 = -1e30f, l0 = 0.f, l1 = 0.f;

    const int rmax_w = qt * 128 + wrow + 15;
    const int ntiles = 2 * qt + 2;

    auto issue = [&](int j, int bf) {
#pragma unroll
        for (int u = 0; u < 4; u++) {
            int fid = u * 256 + tid;
            int r   = fid >> 4;
            int c4  = fid & 15;
            cp_async16(sb + (uint32_t)((bf * A_KBUF + r * A_KW + c4 * 4) * 4),
                       kbase + (size_t)(j * 64 + r) * C3 + c4 * 4);
            cp_async16(sb + (uint32_t)((A_VOFF + bf * A_VBUF + r * A_KW + c4 * 4) * 4),
                       vtb + (size_t)r * SEQ + j * 64 + c4 * 4);
        }
    };

    issue(0, 0);
    cp_commit();

    for (int j0 = 0; j0 < ntiles; j0++) {
        cp_wait0();
        __syncthreads();
        if (j0 + 1 < ntiles) { issue(j0 + 1, (j0 + 1) & 1); cp_commit(); }

        if (j0 * 64 <= rmax_w) {
            const int bf = j0 & 1;
            const uint32_t sbK = sb + (uint32_t)(bf * A_KBUF * 4);
            const uint32_t sbV = sb + (uint32_t)((A_VOFF + bf * A_VBUF) * 4);

            // ---- S = Q K^T (log2-domain scores) ----
            float s[8][4];
#pragma unroll
            for (int nt = 0; nt < 8; nt++)
#pragma unroll
                for (int e = 0; e < 4; e++) s[nt][e] = 0.f;

#pragma unroll
            for (int ks = 0; ks < 8; ks++) {
#pragma unroll
                for (int ntp = 0; ntp < 4; ntp++) {
                    uint32_t kb4[4];
                    ldmx4(kb4, sbK + (uint32_t)(((ntp * 16 + krow_off) * A_KW
                                                 + 8 * ks + kcol_off) * 4));
                    mma16n8k8(s[2 * ntp],     qf[ks], kb4);
                    mma16n8k8(s[2 * ntp + 1], qf[ks], kb4 + 2);
                }
            }

            // ---- causal mask ----
            const int qr0 = qt * 128 + wrow + gid;
            if (j0 * 64 + 63 > qt * 128 + wrow) {
#pragma unroll
                for (int nt = 0; nt < 8; nt++) {
                    const int c0g = j0 * 64 + nt * 8 + 2 * tig;
                    if (c0g     > qr0)     s[nt][0] = -1e30f;
                    if (c0g + 1 > qr0)     s[nt][1] = -1e30f;
                    if (c0g     > qr0 + 8) s[nt][2] = -1e30f;
                    if (c0g + 1 > qr0 + 8) s[nt][3] = -1e30f;
                }
            }

            // ---- online softmax (exp2 domain) ----
            float mloc0 = -1e30f, mloc1 = -1e30f;
#pragma unroll
            for (int nt = 0; nt < 8; nt++) {
                mloc0 = fmaxf(mloc0, fmaxf(s[nt][0], s[nt][1]));
                mloc1 = fmaxf(mloc1, fmaxf(s[nt][2], s[nt][3]));
            }
            mloc0 = fmaxf(mloc0, __shfl_xor_sync(0xffffffffu, mloc0, 1));
            mloc0 = fmaxf(mloc0, __shfl_xor_sync(0xffffffffu, mloc0, 2));
            mloc1 = fmaxf(mloc1, __shfl_xor_sync(0xffffffffu, mloc1, 1));
            mloc1 = fmaxf(mloc1, __shfl_xor_sync(0xffffffffu, mloc1, 2));

            const float mn0 = fmaxf(m0, mloc0);
            const float mn1 = fmaxf(m1, mloc1);
            const float cr0 = ex2(m0 - mn0);
            const float cr1 = ex2(m1 - mn1);
            m0 = mn0;
            m1 = mn1;

#pragma unroll
            for (int nt = 0; nt < 8; nt++) {
                s[nt][0] = ex2(s[nt][0] - mn0);
                s[nt][1] = ex2(s[nt][1] - mn0);
                s[nt][2] = ex2(s[nt][2] - mn1);
                s[nt][3] = ex2(s[nt][3] - mn1);
                o[nt][0] *= cr0; o[nt][1] *= cr0;
                o[nt][2] *= cr1; o[nt][3] *= cr1;
            }

            // ---- stage P (warp-private rows, STS.64) ----
#pragma unroll
            for (int nt = 0; nt < 8; nt++) {
                const int pb = (wrow + gid) * 68 + nt * 8 + 2 * tig;
                uint2 p01, p23;
                p01.x = f2tf32(s[nt][0]);
                p01.y = f2tf32(s[nt][1]);
                p23.x = f2tf32(s[nt][2]);
                p23.y = f2tf32(s[nt][3]);
                *(uint2*)&Ps[pb]          = p01;
                *(uint2*)&Ps[pb + 8 * 68] = p23;
            }
            __syncwarp();

            // ---- O += P V ; l-partials via P @ ones (tensor pipe) ----
            float ls[4] = {0.f, 0.f, 0.f, 0.f};
#pragma unroll
            for (int ks = 0; ks < 8; ks++) {
                uint32_t pa[4];
                ldmx4(pa, sbP + (uint32_t)(((wrow + prow_off) * 68
                                            + 8 * ks + pcol_off) * 4));
                mma16n8k8(ls, pa, bones);
#pragma unroll
                for (int ntp = 0; ntp < 4; ntp++) {
                    uint32_t vb4[4];
                    ldmx4(vb4, sbV + (uint32_t)(((ntp * 16 + krow_off) * A_KW
                                                 + 8 * ks + kcol_off) * 4));
                    mma16n8k8(o[2 * ntp],     pa, vb4);
                    mma16n8k8(o[2 * ntp + 1], pa, vb4 + 2);
                }
            }
            l0 = l0 * cr0 + ls[0];
            l1 = l1 * cr1 + ls[2];
            __syncwarp();
        }
    }

    // ---- normalize + write tf32 bits ----
    const float inv0 = 1.f / l0;
    const float inv1 = 1.f / l1;
    const int t0 = qt * 128 + wrow + gid;
#pragma unroll
    for (int nt = 0; nt < 8; nt++) {
        const int d = h * HD + nt * 8 + 2 * tig;
        uint2 v0, v1;
        v0.x = f2tf32(o[nt][0] * inv0);
        v0.y = f2tf32(o[nt][1] * inv0);
        v1.x = f2tf32(o[nt][2] * inv1);
        v1.y = f2tf32(o[nt][3] * inv1);
        *(uint2*)&attout[(size_t)(b * SEQ + t0) * C_EMBED + d] = v0;
        *(uint2*)&attout[(size_t)(b * SEQ + t0 + 8) * C_EMBED + d] = v1;
    }
}

// ---------------------------------------------------------------------------
extern "C" void kernel_launch(void* const* d_in, const int* in_sizes, int n_in,
                              void* d_out, int out_size)
{
    const float* x     = (const float*)d_in[0];
    const float* Wqkv  = (const float*)d_in[1];
    const float* bqkv  = (const float*)d_in[2];
    const float* Wproj = (const float*)d_in[3];
    const float* bproj = (const float*)d_in[4];
    float* out = (float*)d_out;

    uint32_t *qkv, *vtp, *att, *xt, *wqkvt, *wprojt;
    cudaGetSymbolAddress((void**)&qkv, g_qkv);
    cudaGetSymbolAddress((void**)&vtp, g_vt);
    cudaGetSymbolAddress((void**)&att, g_att);
    cudaGetSymbolAddress((void**)&xt, g_xt);
    cudaGetSymbolAddress((void**)&wqkvt, g_wqkvt);
    cudaGetSymbolAddress((void**)&wprojt, g_wprojt);

    cudaFuncSetAttribute(gemm_tf32_kernel<0>, cudaFuncAttributeMaxDynamicSharedMemorySize,
                         GEMM_SMEM_BYTES);
    cudaFuncSetAttribute(gemm_tf32_kernel<1>, cudaFuncAttributeMaxDynamicSharedMemorySize,
                         GEMM_SMEM_BYTES);
    cudaFuncSetAttribute(attn_tc_kernel, cudaFuncAttributeMaxDynamicSharedMemorySize,
                         ATTN_SMEM_BYTES);

    // 0) pre-round activations; pre-round + TRANSPOSE weights
    {
        int n4x = (MROWS * C_EMBED) / 4;
        cvt_tf32_kernel<<<(n4x + 255) / 256, 256>>>((const float4*)x, (uint4*)xt, n4x);
        dim3 bt(32, 8);
        dim3 gq(C3 / 32, C_EMBED / 32);
        cvt_transpose_kernel<<<gq, bt>>>(Wqkv, wqkvt, C_EMBED, C3);
        dim3 gp(C_EMBED / 32, C_EMBED / 32);
        cvt_transpose_kernel<<<gp, bt>>>(Wproj, wprojt, C_EMBED, C_EMBED);
    }

    // 1) QKV projection -> tf32 bits (Q scaled by 0.125*log2e, V -> g_vt)
    dim3 g1(C3 / 128, MROWS / 128);
    gemm_tf32_kernel<1><<<g1, 256, GEMM_SMEM_BYTES>>>(xt, wqkvt, bqkv, (float*)qkv, vtp,
                                                      MROWS, C3, C_EMBED);

    // 2) Causal flash attention -> tf32 bits
    dim3 g2(SEQ / 128, NH, BATCH);
    attn_tc_kernel<<<g2, 256, ATTN_SMEM_BYTES>>>(qkv, vtp, att);

    // 3) Output projection -> fp32
    dim3 g3(C_EMBED / 128, MROWS / 128);
    gemm_tf32_kernel<0><<<g3, 256, GEMM_SMEM_BYTES>>>(att, wprojt, bproj, out, vtp,
                                                      MROWS, C_EMBED, C_EMBED);
}

// round 16
// speedup vs baseline: 1.0207x; 1.0207x over previous
#include <cuda_runtime.h>
#include <math.h>
#include <stdint.h>

#define C_EMBED 768
#define NH 12
#define HD 64
#define BATCH 2
#define SEQ 4096
#define MROWS (BATCH*SEQ)        // 8192
#define C3 (3*C_EMBED)           // 2304

// Scratch (no allocations allowed) — tf32 bit buffers
__device__ __align__(16) uint32_t g_qkv[(size_t)MROWS * C3];          // 75.5 MB (V third unused)
__device__ __align__(16) uint32_t g_vt[(size_t)MROWS * C_EMBED];      // 25 MB  V^T [b][h][d][t]
__device__ __align__(16) uint32_t g_att[(size_t)MROWS * C_EMBED];     // 25 MB
__device__ __align__(16) uint32_t g_xt[(size_t)MROWS * C_EMBED];      // 25 MB
__device__ __align__(16) uint32_t g_wqkvt[(size_t)C_EMBED * C3];      // 7 MB  W_qkv^T [N][K]
__device__ __align__(16) uint32_t g_wprojt[(size_t)C_EMBED * C_EMBED];// 2.4 MB W_proj^T [N][K]

// ---------------------------------------------------------------------------
// helpers
// ---------------------------------------------------------------------------
__device__ __forceinline__ uint32_t f2tf32(float v) {
    uint32_t t;
    asm("cvt.rna.tf32.f32 %0, %1;" : "=r"(t) : "f"(v));
    return t;
}

__device__ __forceinline__ float ex2(float x) {
    float r;
    asm("ex2.approx.f32 %0, %1;" : "=f"(r) : "f"(x));
    return r;
}

__device__ __forceinline__ void mma16n8k8(float* d, const uint32_t* a, const uint32_t* b) {
    asm volatile(
        "mma.sync.aligned.m16n8k8.row.col.f32.tf32.tf32.f32 "
        "{%0,%1,%2,%3}, {%4,%5,%6,%7}, {%8,%9}, {%0,%1,%2,%3};"
        : "+f"(d[0]), "+f"(d[1]), "+f"(d[2]), "+f"(d[3])
        : "r"(a[0]), "r"(a[1]), "r"(a[2]), "r"(a[3]), "r"(b[0]), "r"(b[1]));
}

// one instruction -> 4 fragment registers (8x4 tf32 blocks)
__device__ __forceinline__ void ldmx4(uint32_t* r, uint32_t a) {
    asm volatile("ldmatrix.sync.aligned.m8n8.x4.shared.b16 {%0,%1,%2,%3}, [%4];"
                 : "=r"(r[0]), "=r"(r[1]), "=r"(r[2]), "=r"(r[3]) : "r"(a));
}

__device__ __forceinline__ uint32_t smem_u32(const void* p) {
    uint32_t a;
    asm("{ .reg .u64 t; cvta.to.shared.u64 t, %1; cvt.u32.u64 %0, t; }"
        : "=r"(a) : "l"(p));
    return a;
}

// .ca restored (R15 showed L1 allocation feeds cross-CTA reuse on-SM)
__device__ __forceinline__ void cp_async16(uint32_t saddr, const void* gptr) {
    asm volatile("cp.async.ca.shared.global [%0], [%1], 16;"
                 :: "r"(saddr), "l"(gptr));
}
__device__ __forceinline__ void cp_commit() {
    asm volatile("cp.async.commit_group;" ::: "memory");
}
__device__ __forceinline__ void cp_wait1() {
    asm volatile("cp.async.wait_group 1;" ::: "memory");
}
__device__ __forceinline__ void cp_wait0() {
    asm volatile("cp.async.wait_group 0;" ::: "memory");
}

// ---------------------------------------------------------------------------
// elementwise fp32 -> tf32-bits pre-pass (activations)
// ---------------------------------------------------------------------------
__global__ void __launch_bounds__(256) cvt_tf32_kernel(
    const float4* __restrict__ in, uint4* __restrict__ out, int n4)
{
    int i = blockIdx.x * blockDim.x + threadIdx.x;
    if (i < n4) {
        float4 v = in[i];
        uint4 t;
        t.x = f2tf32(v.x); t.y = f2tf32(v.y);
        t.z = f2tf32(v.z); t.w = f2tf32(v.w);
        out[i] = t;
    }
}

// fused cvt + transpose for weights: in[K][N] fp32 -> out[N][K] tf32 bits
__global__ void __launch_bounds__(256) cvt_transpose_kernel(
    const float* __restrict__ in, uint32_t* __restrict__ out, int K, int N)
{
    __shared__ uint32_t t[32][33];
    const int n0 = blockIdx.x * 32;
    const int k0 = blockIdx.y * 32;
    const int tx = threadIdx.x;
    const int ty = threadIdx.y;
#pragma unroll
    for (int i = 0; i < 32; i += 8)
        t[ty + i][tx] = f2tf32(in[(size_t)(k0 + ty + i) * N + n0 + tx]);
    __syncthreads();
#pragma unroll
    for (int i = 0; i < 32; i += 8)
        out[(size_t)(n0 + ty + i) * K + k0 + tx] = t[tx][ty + i];
}

// ===========================================================================
// tf32-bit mma GEMM (verified R14 structure, .ca cp.async).
// MODE 1 Q-scale folds 0.125*log2(e) for exp2-domain softmax.
// ===========================================================================
#define G_AW 36
#define G_ABUF (128 * G_AW)
#define G_STG (2 * G_ABUF)
#define GEMM_SMEM_BYTES (2 * G_STG * 4)   // 73728

#define QSCALE_LOG2E 0.1803368867f        // 0.125 * log2(e)

template<int MODE>
__global__ void __launch_bounds__(256, 2) gemm_tf32_kernel(
    const uint32_t* __restrict__ A, const uint32_t* __restrict__ Bt,
    const float* __restrict__ bias, float* __restrict__ Cm,
    uint32_t* __restrict__ Vt,
    int M, int N, int K)
{
    extern __shared__ uint32_t gsm[];
    const uint32_t sb = smem_u32(gsm);

    const int tid = threadIdx.x;
    const int w   = tid >> 5;
    const int L   = tid & 31;
    const int gid = L >> 2;
    const int tig = L & 3;
    const int row0 = blockIdx.y * 128;
    const int col0 = blockIdx.x * 128;
    const int m0w = (w & 1) * 64;
    const int n0w = (w >> 1) * 32;
    const int nk = K >> 5;

    const int am = L >> 3;
    const int arow_off = ((am & 1) << 3) + (L & 7);
    const int acol_off = (am >> 1) << 2;
    const int bm = L >> 3;
    const int brow_off = ((bm >> 1) << 3) + (L & 7);
    const int bcol_off = (bm & 1) << 2;

    float acc[4][4][4];
#pragma unroll
    for (int mt = 0; mt < 4; mt++)
#pragma unroll
        for (int nt = 0; nt < 4; nt++)
#pragma unroll
            for (int e = 0; e < 4; e++) acc[mt][nt][e] = 0.f;

    auto issue = [&](int t, int bf) {
        const int kb = t * 32;
        const uint32_t base = sb + (uint32_t)(bf * G_STG * 4);
#pragma unroll
        for (int u = 0; u < 4; u++) {
            int fid = u * 256 + tid;
            int r   = fid >> 3;
            int c4  = fid & 7;
            cp_async16(base + (uint32_t)((r * G_AW + c4 * 4) * 4),
                       &A[(size_t)(row0 + r) * K + kb + c4 * 4]);
        }
#pragma unroll
        for (int u = 0; u < 4; u++) {
            int fid = u * 256 + tid;
            int r   = fid >> 3;
            int c4  = fid & 7;
            cp_async16(base + (uint32_t)((G_ABUF + r * G_AW + c4 * 4) * 4),
                       &Bt[(size_t)(col0 + r) * K + kb + c4 * 4]);
        }
    };

    issue(0, 0);
    cp_commit();

    for (int t = 0; t < nk; t++) {
        const int bf = t & 1;
        if (t + 1 < nk) { issue(t + 1, bf ^ 1); cp_commit(); cp_wait1(); }
        else            { cp_wait0(); }
        __syncthreads();

        const uint32_t sbA = sb + (uint32_t)(bf * G_STG * 4);
        const uint32_t sbB = sbA + (uint32_t)(G_ABUF * 4);

#pragma unroll
        for (int ks = 0; ks < 4; ks++) {
            const int k0 = ks * 8;
            uint32_t af[4][4];
#pragma unroll
            for (int mt = 0; mt < 4; mt++) {
                ldmx4(af[mt], sbA + (uint32_t)(((m0w + mt * 16 + arow_off) * G_AW
                                                + k0 + acol_off) * 4));
            }
            uint32_t bfr[4][2];
#pragma unroll
            for (int ntp = 0; ntp < 2; ntp++) {
                uint32_t bt4[4];
                ldmx4(bt4, sbB + (uint32_t)(((n0w + ntp * 16 + brow_off) * G_AW
                                             + k0 + bcol_off) * 4));
                bfr[2 * ntp][0]     = bt4[0];
                bfr[2 * ntp][1]     = bt4[1];
                bfr[2 * ntp + 1][0] = bt4[2];
                bfr[2 * ntp + 1][1] = bt4[3];
            }
#pragma unroll
            for (int mt = 0; mt < 4; mt++)
#pragma unroll
                for (int nt = 0; nt < 4; nt++)
                    mma16n8k8(acc[mt][nt], af[mt], bfr[nt]);
        }
        __syncthreads();
    }

    // epilogue
#pragma unroll
    for (int mt = 0; mt < 4; mt++) {
        const int r = row0 + m0w + mt * 16 + gid;
#pragma unroll
        for (int nt = 0; nt < 4; nt++) {
            const int c = col0 + n0w + nt * 8 + 2 * tig;
            const float b0 = bias[c], b1 = bias[c + 1];
            if (MODE == 0) {
                float2 v0 = make_float2(acc[mt][nt][0] + b0, acc[mt][nt][1] + b1);
                *(float2*)&Cm[(size_t)r * N + c] = v0;
                float2 v1 = make_float2(acc[mt][nt][2] + b0, acc[mt][nt][3] + b1);
                *(float2*)&Cm[(size_t)(r + 8) * N + c] = v1;
            } else {
                uint2 v0, v1;
                if (c < 2 * C_EMBED) {
                    const float sc = (c < C_EMBED) ? QSCALE_LOG2E : 1.0f;
                    v0.x = f2tf32((acc[mt][nt][0] + b0) * sc);
                    v0.y = f2tf32((acc[mt][nt][1] + b1) * sc);
                    v1.x = f2tf32((acc[mt][nt][2] + b0) * sc);
                    v1.y = f2tf32((acc[mt][nt][3] + b1) * sc);
                    uint32_t* Co = (uint32_t*)Cm;
                    *(uint2*)&Co[(size_t)r * N + c] = v0;
                    *(uint2*)&Co[(size_t)(r + 8) * N + c] = v1;
                } else {
                    // V block -> transposed store Vt[b][h][d][t]
                    v0.x = f2tf32(acc[mt][nt][0] + b0);
                    v0.y = f2tf32(acc[mt][nt][1] + b1);
                    v1.x = f2tf32(acc[mt][nt][2] + b0);
                    v1.y = f2tf32(acc[mt][nt][3] + b1);
                    const int hd = c - 2 * C_EMBED;
                    const int hh = hd >> 6;
                    const int d  = hd & 63;
                    const int bb = r >> 12;
                    const int tt = r & 4095;
                    const size_t base = ((size_t)(bb * NH + hh) * HD + d) * SEQ + tt;
                    Vt[base]           = v0.x;
                    Vt[base + SEQ]     = v0.y;
                    Vt[base + 8]       = v1.x;
                    Vt[base + SEQ + 8] = v1.y;
                }
            }
        }
    }
}

// ===========================================================================
// tf32-bit mma flash attention (causal), exp2-domain softmax, l via P@ones.
// NEW: warp-uniform ballot skip of the o-rescale when no row max changed
// (cr == 1.0 exactly in that case -> bit-identical results).
// ===========================================================================
#define A_KW 68
#define A_KBUF (64 * A_KW)
#define A_VBUF (64 * A_KW)
#define A_VOFF (2 * A_KBUF)
#define A_POFF (A_VOFF + 2 * A_VBUF)
#define ATTN_SMEM_BYTES ((A_POFF + 128 * 68) * 4)   // 104448

__global__ void __launch_bounds__(256) attn_tc_kernel(
    const uint32_t* __restrict__ qkv, const uint32_t* __restrict__ vt,
    uint32_t* __restrict__ attout)
{
    extern __shared__ uint32_t asm_[];
    const uint32_t sb = smem_u32(asm_);
    uint32_t* Ps = asm_ + A_POFF;
    const uint32_t sbP = sb + (uint32_t)(A_POFF * 4);

    const int qt  = (int)gridDim.x - 1 - (int)blockIdx.x;   // largest-first
    const int h   = blockIdx.y;
    const int b   = blockIdx.z;
    const int tid = threadIdx.x;
    const int w   = tid >> 5;
    const int L   = tid & 31;
    const int gid = L >> 2;
    const int tig = L & 3;
    const int wrow = w * 16;

    const int km = L >> 3;
    const int krow_off = ((km >> 1) << 3) + (L & 7);
    const int kcol_off = (km & 1) << 2;
    const int pm = L >> 3;
    const int prow_off = ((pm & 1) << 3) + (L & 7);
    const int pcol_off = (pm >> 1) << 2;

    const uint32_t* qbase = qkv + (size_t)b * SEQ * C3 + h * HD;
    const uint32_t* kbase = qbase + C_EMBED;
    const uint32_t* vtb   = vt + (size_t)(b * NH + h) * HD * SEQ;

    // ones B-fragment for row-sum mma (tf32 bits of 1.0f)
    const uint32_t bones[2] = { 0x3F800000u, 0x3F800000u };

    // ---- Q fragments ----
    uint32_t qf[8][4];
    {
        const uint32_t* qr0 = qbase + (size_t)(qt * 128 + wrow + gid) * C3;
        const uint32_t* qr1 = qr0 + 8 * C3;
#pragma unroll
        for (int ks = 0; ks < 8; ks++) {
            const int c = 8 * ks + tig;
            qf[ks][0] = qr0[c];
            qf[ks][1] = qr1[c];
            qf[ks][2] = qr0[c + 4];
            qf[ks][3] = qr1[c + 4];
        }
    }

    float o[8][4];
#pragma unroll
    for (int nt = 0; nt < 8; nt++)
#pragma unroll
        for (int e = 0; e < 4; e++) o[nt][e] = 0.f;
    float m0 = -1e30f, m1 = -1e30f, l0 = 0.f, l1 = 0.f;

    const int rmax_w = qt * 128 + wrow + 15;
    const int ntiles = 2 * qt + 2;

    auto issue = [&](int j, int bf) {
#pragma unroll
        for (int u = 0; u < 4; u++) {
            int fid = u * 256 + tid;
            int r   = fid >> 4;
            int c4  = fid & 15;
            cp_async16(sb + (uint32_t)((bf * A_KBUF + r * A_KW + c4 * 4) * 4),
                       kbase + (size_t)(j * 64 + r) * C3 + c4 * 4);
            cp_async16(sb + (uint32_t)((A_VOFF + bf * A_VBUF + r * A_KW + c4 * 4) * 4),
                       vtb + (size_t)r * SEQ + j * 64 + c4 * 4);
        }
    };

    issue(0, 0);
    cp_commit();

    for (int j0 = 0; j0 < ntiles; j0++) {
        cp_wait0();
        __syncthreads();
        if (j0 + 1 < ntiles) { issue(j0 + 1, (j0 + 1) & 1); cp_commit(); }

        if (j0 * 64 <= rmax_w) {
            const int bf = j0 & 1;
            const uint32_t sbK = sb + (uint32_t)(bf * A_KBUF * 4);
            const uint32_t sbV = sb + (uint32_t)((A_VOFF + bf * A_VBUF) * 4);

            // ---- S = Q K^T (log2-domain scores) ----
            float s[8][4];
#pragma unroll
            for (int nt = 0; nt < 8; nt++)
#pragma unroll
                for (int e = 0; e < 4; e++) s[nt][e] = 0.f;

#pragma unroll
            for (int ks = 0; ks < 8; ks++) {
#pragma unroll
                for (int ntp = 0; ntp < 4; ntp++) {
                    uint32_t kb4[4];
                    ldmx4(kb4, sbK + (uint32_t)(((ntp * 16 + krow_off) * A_KW
                                                 + 8 * ks + kcol_off) * 4));
                    mma16n8k8(s[2 * ntp],     qf[ks], kb4);
                    mma16n8k8(s[2 * ntp + 1], qf[ks], kb4 + 2);
                }
            }

            // ---- causal mask ----
            const int qr0 = qt * 128 + wrow + gid;
            if (j0 * 64 + 63 > qt * 128 + wrow) {
#pragma unroll
                for (int nt = 0; nt < 8; nt++) {
                    const int c0g = j0 * 64 + nt * 8 + 2 * tig;
                    if (c0g     > qr0)     s[nt][0] = -1e30f;
                    if (c0g + 1 > qr0)     s[nt][1] = -1e30f;
                    if (c0g     > qr0 + 8) s[nt][2] = -1e30f;
                    if (c0g + 1 > qr0 + 8) s[nt][3] = -1e30f;
                }
            }

            // ---- online softmax (exp2 domain) ----
            float mloc0 = -1e30f, mloc1 = -1e30f;
#pragma unroll
            for (int nt = 0; nt < 8; nt++) {
                mloc0 = fmaxf(mloc0, fmaxf(s[nt][0], s[nt][1]));
                mloc1 = fmaxf(mloc1, fmaxf(s[nt][2], s[nt][3]));
            }
            mloc0 = fmaxf(mloc0, __shfl_xor_sync(0xffffffffu, mloc0, 1));
            mloc0 = fmaxf(mloc0, __shfl_xor_sync(0xffffffffu, mloc0, 2));
            mloc1 = fmaxf(mloc1, __shfl_xor_sync(0xffffffffu, mloc1, 1));
            mloc1 = fmaxf(mloc1, __shfl_xor_sync(0xffffffffu, mloc1, 2));

            const float mn0 = fmaxf(m0, mloc0);
            const float mn1 = fmaxf(m1, mloc1);

            // warp-uniform rescale skip: cr==1.0 exactly when max unchanged
            float cr0 = 1.f, cr1 = 1.f;
            const unsigned chg = __ballot_sync(0xffffffffu,
                                               (mn0 > m0) | (mn1 > m1));
            if (chg) {
                cr0 = ex2(m0 - mn0);
                cr1 = ex2(m1 - mn1);
#pragma unroll
                for (int nt = 0; nt < 8; nt++) {
                    o[nt][0] *= cr0; o[nt][1] *= cr0;
                    o[nt][2] *= cr1; o[nt][3] *= cr1;
                }
            }
            m0 = mn0;
            m1 = mn1;

#pragma unroll
            for (int nt = 0; nt < 8; nt++) {
                s[nt][0] = ex2(s[nt][0] - mn0);
                s[nt][1] = ex2(s[nt][1] - mn0);
                s[nt][2] = ex2(s[nt][2] - mn1);
                s[nt][3] = ex2(s[nt][3] - mn1);
            }

            // ---- stage P (warp-private rows, STS.64) ----
#pragma unroll
            for (int nt = 0; nt < 8; nt++) {
                const int pb = (wrow + gid) * 68 + nt * 8 + 2 * tig;
                uint2 p01, p23;
                p01.x = f2tf32(s[nt][0]);
                p01.y = f2tf32(s[nt][1]);
                p23.x = f2tf32(s[nt][2]);
                p23.y = f2tf32(s[nt][3]);
                *(uint2*)&Ps[pb]          = p01;
                *(uint2*)&Ps[pb + 8 * 68] = p23;
            }
            __syncwarp();

            // ---- O += P V ; l-partials via P @ ones (tensor pipe) ----
            float ls[4] = {0.f, 0.f, 0.f, 0.f};
#pragma unroll
            for (int ks = 0; ks < 8; ks++) {
                uint32_t pa[4];
                ldmx4(pa, sbP + (uint32_t)(((wrow + prow_off) * 68
                                            + 8 * ks + pcol_off) * 4));
                mma16n8k8(ls, pa, bones);
#pragma unroll
                for (int ntp = 0; ntp < 4; ntp++) {
                    uint32_t vb4[4];
                    ldmx4(vb4, sbV + (uint32_t)(((ntp * 16 + krow_off) * A_KW
                                                 + 8 * ks + kcol_off) * 4));
                    mma16n8k8(o[2 * ntp],     pa, vb4);
                    mma16n8k8(o[2 * ntp + 1], pa, vb4 + 2);
                }
            }
            l0 = l0 * cr0 + ls[0];
            l1 = l1 * cr1 + ls[2];
            __syncwarp();
        }
    }

    // ---- normalize + write tf32 bits ----
    const float inv0 = 1.f / l0;
    const float inv1 = 1.f / l1;
    const int t0 = qt * 128 + wrow + gid;
#pragma unroll
    for (int nt = 0; nt < 8; nt++) {
        const int d = h * HD + nt * 8 + 2 * tig;
        uint2 v0, v1;
        v0.x = f2tf32(o[nt][0] * inv0);
        v0.y = f2tf32(o[nt][1] * inv0);
        v1.x = f2tf32(o[nt][2] * inv1);
        v1.y = f2tf32(o[nt][3] * inv1);
        *(uint2*)&attout[(size_t)(b * SEQ + t0) * C_EMBED + d] = v0;
        *(uint2*)&attout[(size_t)(b * SEQ + t0 + 8) * C_EMBED + d] = v1;
    }
}

// ---------------------------------------------------------------------------
extern "C" void kernel_launch(void* const* d_in, const int* in_sizes, int n_in,
                              void* d_out, int out_size)
{
    const float* x     = (const float*)d_in[0];
    const float* Wqkv  = (const float*)d_in[1];
    const float* bqkv  = (const float*)d_in[2];
    const float* Wproj = (const float*)d_in[3];
    const float* bproj = (const float*)d_in[4];
    float* out = (float*)d_out;

    uint32_t *qkv, *vtp, *att, *xt, *wqkvt, *wprojt;
    cudaGetSymbolAddress((void**)&qkv, g_qkv);
    cudaGetSymbolAddress((void**)&vtp, g_vt);
    cudaGetSymbolAddress((void**)&att, g_att);
    cudaGetSymbolAddress((void**)&xt, g_xt);
    cudaGetSymbolAddress((void**)&wqkvt, g_wqkvt);
    cudaGetSymbolAddress((void**)&wprojt, g_wprojt);

    cudaFuncSetAttribute(gemm_tf32_kernel<0>, cudaFuncAttributeMaxDynamicSharedMemorySize,
                         GEMM_SMEM_BYTES);
    cudaFuncSetAttribute(gemm_tf32_kernel<1>, cudaFuncAttributeMaxDynamicSharedMemorySize,
                         GEMM_SMEM_BYTES);
    cudaFuncSetAttribute(attn_tc_kernel, cudaFuncAttributeMaxDynamicSharedMemorySize,
                         ATTN_SMEM_BYTES);

    // 0) pre-round activations; pre-round + TRANSPOSE weights
    {
        int n4x = (MROWS * C_EMBED) / 4;
        cvt_tf32_kernel<<<(n4x + 255) / 256, 256>>>((const float4*)x, (uint4*)xt, n4x);
        dim3 bt(32, 8);
        dim3 gq(C3 / 32, C_EMBED / 32);
        cvt_transpose_kernel<<<gq, bt>>>(Wqkv, wqkvt, C_EMBED, C3);
        dim3 gp(C_EMBED / 32, C_EMBED / 32);
        cvt_transpose_kernel<<<gp, bt>>>(Wproj, wprojt, C_EMBED, C_EMBED);
    }

    // 1) QKV projection -> tf32 bits (Q scaled by 0.125*log2e, V -> g_vt)
    dim3 g1(C3 / 128, MROWS / 128);
    gemm_tf32_kernel<1><<<g1, 256, GEMM_SMEM_BYTES>>>(xt, wqkvt, bqkv, (float*)qkv, vtp,
                                                      MROWS, C3, C_EMBED);

    // 2) Causal flash attention -> tf32 bits
    dim3 g2(SEQ / 128, NH, BATCH);
    attn_tc_kernel<<<g2, 256, ATTN_SMEM_BYTES>>>(qkv, vtp, att);

    // 3) Output projection -> fp32
    dim3 g3(C_EMBED / 128, MROWS / 128);
    gemm_tf32_kernel<0><<<g3, 256, GEMM_SMEM_BYTES>>>(att, wprojt, bproj, out, vtp,
                                                      MROWS, C_EMBED, C_EMBED);
}

// round 17
// speedup vs baseline: 1.2343x; 1.2092x over previous
#include <cuda_runtime.h>
#include <cuda_fp16.h>
#include <math.h>
#include <stdint.h>

#define C_EMBED 768
#define NH 12
#define HD 64
#define BATCH 2
#define SEQ 4096
#define MROWS (BATCH*SEQ)        // 8192
#define C3 (3*C_EMBED)           // 2304

// Scratch (no allocations allowed)
__device__ __align__(16) uint32_t g_qkv[(size_t)MROWS * C3];          // 75.5 MB (V third unused)
__device__ __align__(16) uint32_t g_vt[(size_t)MROWS * C_EMBED / 2];  // 12.5 MB V^T fp16 [b][h][d][t]
__device__ __align__(16) uint32_t g_att[(size_t)MROWS * C_EMBED];     // 25 MB
__device__ __align__(16) uint32_t g_xt[(size_t)MROWS * C_EMBED];      // 25 MB
__device__ __align__(16) uint32_t g_wqkvt[(size_t)C_EMBED * C3];      // 7 MB  W_qkv^T [N][K]
__device__ __align__(16) uint32_t g_wprojt[(size_t)C_EMBED * C_EMBED];// 2.4 MB W_proj^T [N][K]

// ---------------------------------------------------------------------------
// helpers
// ---------------------------------------------------------------------------
__device__ __forceinline__ uint32_t f2tf32(float v) {
    uint32_t t;
    asm("cvt.rna.tf32.f32 %0, %1;" : "=r"(t) : "f"(v));
    return t;
}

__device__ __forceinline__ float ex2(float x) {
    float r;
    asm("ex2.approx.f32 %0, %1;" : "=f"(r) : "f"(x));
    return r;
}

// pack (lo, hi) floats into one f16x2 word
__device__ __forceinline__ uint32_t f2h2(float lo, float hi) {
    uint32_t r;
    asm("cvt.rn.f16x2.f32 %0, %1, %2;" : "=r"(r) : "f"(hi), "f"(lo));
    return r;
}

__device__ __forceinline__ void mma16n8k8(float* d, const uint32_t* a, const uint32_t* b) {
    asm volatile(
        "mma.sync.aligned.m16n8k8.row.col.f32.tf32.tf32.f32 "
        "{%0,%1,%2,%3}, {%4,%5,%6,%7}, {%8,%9}, {%0,%1,%2,%3};"
        : "+f"(d[0]), "+f"(d[1]), "+f"(d[2]), "+f"(d[3])
        : "r"(a[0]), "r"(a[1]), "r"(a[2]), "r"(a[3]), "r"(b[0]), "r"(b[1]));
}

__device__ __forceinline__ void mma16n8k16h(float* d, const uint32_t* a, const uint32_t* b) {
    asm volatile(
        "mma.sync.aligned.m16n8k16.row.col.f32.f16.f16.f32 "
        "{%0,%1,%2,%3}, {%4,%5,%6,%7}, {%8,%9}, {%0,%1,%2,%3};"
        : "+f"(d[0]), "+f"(d[1]), "+f"(d[2]), "+f"(d[3])
        : "r"(a[0]), "r"(a[1]), "r"(a[2]), "r"(a[3]), "r"(b[0]), "r"(b[1]));
}

// one instruction -> 4 fragment registers
__device__ __forceinline__ void ldmx4(uint32_t* r, uint32_t a) {
    asm volatile("ldmatrix.sync.aligned.m8n8.x4.shared.b16 {%0,%1,%2,%3}, [%4];"
                 : "=r"(r[0]), "=r"(r[1]), "=r"(r[2]), "=r"(r[3]) : "r"(a));
}

__device__ __forceinline__ uint32_t smem_u32(const void* p) {
    uint32_t a;
    asm("{ .reg .u64 t; cvta.to.shared.u64 t, %1; cvt.u32.u64 %0, t; }"
        : "=r"(a) : "l"(p));
    return a;
}

__device__ __forceinline__ void cp_async16(uint32_t saddr, const void* gptr) {
    asm volatile("cp.async.ca.shared.global [%0], [%1], 16;"
                 :: "r"(saddr), "l"(gptr));
}
__device__ __forceinline__ void cp_commit() {
    asm volatile("cp.async.commit_group;" ::: "memory");
}
__device__ __forceinline__ void cp_wait1() {
    asm volatile("cp.async.wait_group 1;" ::: "memory");
}
__device__ __forceinline__ void cp_wait0() {
    asm volatile("cp.async.wait_group 0;" ::: "memory");
}

// ---------------------------------------------------------------------------
// elementwise fp32 -> tf32-bits pre-pass (activations)
// ---------------------------------------------------------------------------
__global__ void __launch_bounds__(256) cvt_tf32_kernel(
    const float4* __restrict__ in, uint4* __restrict__ out, int n4)
{
    int i = blockIdx.x * blockDim.x + threadIdx.x;
    if (i < n4) {
        float4 v = in[i];
        uint4 t;
        t.x = f2tf32(v.x); t.y = f2tf32(v.y);
        t.z = f2tf32(v.z); t.w = f2tf32(v.w);
        out[i] = t;
    }
}

// fused cvt + transpose for weights: in[K][N] fp32 -> out[N][K] tf32 bits
__global__ void __launch_bounds__(256) cvt_transpose_kernel(
    const float* __restrict__ in, uint32_t* __restrict__ out, int K, int N)
{
    __shared__ uint32_t t[32][33];
    const int n0 = blockIdx.x * 32;
    const int k0 = blockIdx.y * 32;
    const int tx = threadIdx.x;
    const int ty = threadIdx.y;
#pragma unroll
    for (int i = 0; i < 32; i += 8)
        t[ty + i][tx] = f2tf32(in[(size_t)(k0 + ty + i) * N + n0 + tx]);
    __syncthreads();
#pragma unroll
    for (int i = 0; i < 32; i += 8)
        out[(size_t)(n0 + ty + i) * K + k0 + tx] = t[tx][ty + i];
}

// ===========================================================================
// tf32-bit mma GEMM (verified R14 structure, .ca cp.async).
// MODE 1: Q cols scaled 0.125*log2e (tf32 bits), K in-place (tf32 bits),
// V cols -> FP16 transposed store Vt_h[b][h][d][t].
// ===========================================================================
#define G_AW 36
#define G_ABUF (128 * G_AW)
#define G_STG (2 * G_ABUF)
#define GEMM_SMEM_BYTES (2 * G_STG * 4)   // 73728

#define QSCALE_LOG2E 0.1803368867f        // 0.125 * log2(e)

template<int MODE>
__global__ void __launch_bounds__(256, 2) gemm_tf32_kernel(
    const uint32_t* __restrict__ A, const uint32_t* __restrict__ Bt,
    const float* __restrict__ bias, float* __restrict__ Cm,
    uint32_t* __restrict__ Vt,
    int M, int N, int K)
{
    extern __shared__ uint32_t gsm[];
    const uint32_t sb = smem_u32(gsm);

    const int tid = threadIdx.x;
    const int w   = tid >> 5;
    const int L   = tid & 31;
    const int gid = L >> 2;
    const int tig = L & 3;
    const int row0 = blockIdx.y * 128;
    const int col0 = blockIdx.x * 128;
    const int m0w = (w & 1) * 64;
    const int n0w = (w >> 1) * 32;
    const int nk = K >> 5;

    const int am = L >> 3;
    const int arow_off = ((am & 1) << 3) + (L & 7);
    const int acol_off = (am >> 1) << 2;
    const int bm = L >> 3;
    const int brow_off = ((bm >> 1) << 3) + (L & 7);
    const int bcol_off = (bm & 1) << 2;

    float acc[4][4][4];
#pragma unroll
    for (int mt = 0; mt < 4; mt++)
#pragma unroll
        for (int nt = 0; nt < 4; nt++)
#pragma unroll
            for (int e = 0; e < 4; e++) acc[mt][nt][e] = 0.f;

    auto issue = [&](int t, int bf) {
        const int kb = t * 32;
        const uint32_t base = sb + (uint32_t)(bf * G_STG * 4);
#pragma unroll
        for (int u = 0; u < 4; u++) {
            int fid = u * 256 + tid;
            int r   = fid >> 3;
            int c4  = fid & 7;
            cp_async16(base + (uint32_t)((r * G_AW + c4 * 4) * 4),
                       &A[(size_t)(row0 + r) * K + kb + c4 * 4]);
        }
#pragma unroll
        for (int u = 0; u < 4; u++) {
            int fid = u * 256 + tid;
            int r   = fid >> 3;
            int c4  = fid & 7;
            cp_async16(base + (uint32_t)((G_ABUF + r * G_AW + c4 * 4) * 4),
                       &Bt[(size_t)(col0 + r) * K + kb + c4 * 4]);
        }
    };

    issue(0, 0);
    cp_commit();

    for (int t = 0; t < nk; t++) {
        const int bf = t & 1;
        if (t + 1 < nk) { issue(t + 1, bf ^ 1); cp_commit(); cp_wait1(); }
        else            { cp_wait0(); }
        __syncthreads();

        const uint32_t sbA = sb + (uint32_t)(bf * G_STG * 4);
        const uint32_t sbB = sbA + (uint32_t)(G_ABUF * 4);

#pragma unroll
        for (int ks = 0; ks < 4; ks++) {
            const int k0 = ks * 8;
            uint32_t af[4][4];
#pragma unroll
            for (int mt = 0; mt < 4; mt++) {
                ldmx4(af[mt], sbA + (uint32_t)(((m0w + mt * 16 + arow_off) * G_AW
                                                + k0 + acol_off) * 4));
            }
            uint32_t bfr[4][2];
#pragma unroll
            for (int ntp = 0; ntp < 2; ntp++) {
                uint32_t bt4[4];
                ldmx4(bt4, sbB + (uint32_t)(((n0w + ntp * 16 + brow_off) * G_AW
                                             + k0 + bcol_off) * 4));
                bfr[2 * ntp][0]     = bt4[0];
                bfr[2 * ntp][1]     = bt4[1];
                bfr[2 * ntp + 1][0] = bt4[2];
                bfr[2 * ntp + 1][1] = bt4[3];
            }
#pragma unroll
            for (int mt = 0; mt < 4; mt++)
#pragma unroll
                for (int nt = 0; nt < 4; nt++)
                    mma16n8k8(acc[mt][nt], af[mt], bfr[nt]);
        }
        __syncthreads();
    }

    // epilogue
#pragma unroll
    for (int mt = 0; mt < 4; mt++) {
        const int r = row0 + m0w + mt * 16 + gid;
#pragma unroll
        for (int nt = 0; nt < 4; nt++) {
            const int c = col0 + n0w + nt * 8 + 2 * tig;
            const float b0 = bias[c], b1 = bias[c + 1];
            if (MODE == 0) {
                float2 v0 = make_float2(acc[mt][nt][0] + b0, acc[mt][nt][1] + b1);
                *(float2*)&Cm[(size_t)r * N + c] = v0;
                float2 v1 = make_float2(acc[mt][nt][2] + b0, acc[mt][nt][3] + b1);
                *(float2*)&Cm[(size_t)(r + 8) * N + c] = v1;
            } else {
                if (c < 2 * C_EMBED) {
                    const float sc = (c < C_EMBED) ? QSCALE_LOG2E : 1.0f;
                    uint2 v0, v1;
                    v0.x = f2tf32((acc[mt][nt][0] + b0) * sc);
                    v0.y = f2tf32((acc[mt][nt][1] + b1) * sc);
                    v1.x = f2tf32((acc[mt][nt][2] + b0) * sc);
                    v1.y = f2tf32((acc[mt][nt][3] + b1) * sc);
                    uint32_t* Co = (uint32_t*)Cm;
                    *(uint2*)&Co[(size_t)r * N + c] = v0;
                    *(uint2*)&Co[(size_t)(r + 8) * N + c] = v1;
                } else {
                    // V block -> FP16 transposed store Vt_h[b][h][d][t]
                    __half* Vh = (__half*)Vt;
                    const int hd = c - 2 * C_EMBED;
                    const int hh = hd >> 6;
                    const int d  = hd & 63;
                    const int bb = r >> 12;
                    const int tt = r & 4095;
                    const size_t base = ((size_t)(bb * NH + hh) * HD + d) * SEQ + tt;
                    Vh[base]           = __float2half_rn(acc[mt][nt][0] + b0);  // (d,   t)
                    Vh[base + SEQ]     = __float2half_rn(acc[mt][nt][1] + b1);  // (d+1, t)
                    Vh[base + 8]       = __float2half_rn(acc[mt][nt][2] + b0);  // (d,   t+8)
                    Vh[base + SEQ + 8] = __float2half_rn(acc[mt][nt][3] + b1);  // (d+1, t+8)
                }
            }
        }
    }
}

// ===========================================================================
// flash attention (causal): QK in tf32, softmax exp2-domain (R14 verified),
// PV in FP16 (m16n8k16): V fp16 [dim][key] smem, P fp16 staged, l via P@ones.
// ===========================================================================
#define A_KW 68
#define A_KBUF (64 * A_KW)                 // K tile (tf32 words)
#define A_VW 36                            // V tile row stride in WORDS (72 halves)
#define A_VBUF (64 * A_VW)                 // V tile (fp16, 64 dims x 64 keys)
#define A_PW 36                            // P row stride in WORDS (72 halves)
#define A_VOFF (2 * A_KBUF)
#define A_POFF (A_VOFF + 2 * A_VBUF)
#define ATTN_SMEM_BYTES ((A_POFF + 128 * A_PW) * 4)   // 71680

__global__ void __launch_bounds__(256) attn_tc_kernel(
    const uint32_t* __restrict__ qkv, const uint32_t* __restrict__ vt,
    uint32_t* __restrict__ attout)
{
    extern __shared__ uint32_t asm_[];
    const uint32_t sb = smem_u32(asm_);
    uint32_t* Ps = asm_ + A_POFF;
    const uint32_t sbP = sb + (uint32_t)(A_POFF * 4);

    const int qt  = (int)gridDim.x - 1 - (int)blockIdx.x;   // largest-first
    const int h   = blockIdx.y;
    const int b   = blockIdx.z;
    const int tid = threadIdx.x;
    const int w   = tid >> 5;
    const int L   = tid & 31;
    const int gid = L >> 2;
    const int tig = L & 3;
    const int wrow = w * 16;

    // tf32 K ldmatrix map (verified)
    const int km = L >> 3;
    const int krow_off = ((km >> 1) << 3) + (L & 7);
    const int kcol_off = (km & 1) << 2;
    // fp16 P (A-op) map: row = wrow + ((m&1)<<3)+(L&7), col halves = ((m>>1)<<3)
    const int pm = L >> 3;
    const int prow_off = ((pm & 1) << 3) + (L & 7);
    const int pcol_off = (pm >> 1) << 3;       // in halves
    // fp16 V (B-op) map: row(dim) = ((m>>1)<<3)+(L&7), col halves = ((m&1)<<3)
    const int vrow_off = ((pm >> 1) << 3) + (L & 7);
    const int vcol_off = (pm & 1) << 3;        // in halves

    const uint32_t* qbase = qkv + (size_t)b * SEQ * C3 + h * HD;
    const uint32_t* kbase = qbase + C_EMBED;
    const __half* vtb = (const __half*)vt + (size_t)(b * NH + h) * HD * SEQ;

    // fp16 ones B-fragment for row-sum mma
    const uint32_t hones[2] = { 0x3C003C00u, 0x3C003C00u };

    // ---- Q fragments (tf32 bits) ----
    uint32_t qf[8][4];
    {
        const uint32_t* qr0 = qbase + (size_t)(qt * 128 + wrow + gid) * C3;
        const uint32_t* qr1 = qr0 + 8 * C3;
#pragma unroll
        for (int ks = 0; ks < 8; ks++) {
            const int c = 8 * ks + tig;
            qf[ks][0] = qr0[c];
            qf[ks][1] = qr1[c];
            qf[ks][2] = qr0[c + 4];
            qf[ks][3] = qr1[c + 4];
        }
    }

    float o[8][4];
#pragma unroll
    for (int nt = 0; nt < 8; nt++)
#pragma unroll
        for (int e = 0; e < 4; e++) o[nt][e] = 0.f;
    float m0 = -1e30f, m1 = -1e30f, l0 = 0.f, l1 = 0.f;

    const int rmax_w = qt * 128 + wrow + 15;
    const int ntiles = 2 * qt + 2;

    auto issue = [&](int j, int bf) {
        // K: 1024 16B chunks, 4/thread (tf32)
#pragma unroll
        for (int u = 0; u < 4; u++) {
            int fid = u * 256 + tid;
            int r   = fid >> 4;
            int c4  = fid & 15;
            cp_async16(sb + (uint32_t)((bf * A_KBUF + r * A_KW + c4 * 4) * 4),
                       kbase + (size_t)(j * 64 + r) * C3 + c4 * 4);
        }
        // V: 512 16B chunks, 2/thread (fp16: row=dim, 64 halves=8 chunks)
#pragma unroll
        for (int u = 0; u < 2; u++) {
            int fid = u * 256 + tid;
            int r   = fid >> 3;              // dim 0..63
            int c   = fid & 7;               // 16B chunk = 8 halves
            cp_async16(sb + (uint32_t)((A_VOFF + bf * A_VBUF + r * A_VW + c * 4) * 4),
                       vtb + (size_t)r * SEQ + j * 64 + c * 8);
        }
    };

    issue(0, 0);
    cp_commit();

    for (int j0 = 0; j0 < ntiles; j0++) {
        cp_wait0();
        __syncthreads();
        if (j0 + 1 < ntiles) { issue(j0 + 1, (j0 + 1) & 1); cp_commit(); }

        if (j0 * 64 <= rmax_w) {
            const int bf = j0 & 1;
            const uint32_t sbK = sb + (uint32_t)(bf * A_KBUF * 4);
            const uint32_t sbV = sb + (uint32_t)((A_VOFF + bf * A_VBUF) * 4);

            // ---- S = Q K^T (tf32, log2-domain scores) ----
            float s[8][4];
#pragma unroll
            for (int nt = 0; nt < 8; nt++)
#pragma unroll
                for (int e = 0; e < 4; e++) s[nt][e] = 0.f;

#pragma unroll
            for (int ks = 0; ks < 8; ks++) {
#pragma unroll
                for (int ntp = 0; ntp < 4; ntp++) {
                    uint32_t kb4[4];
                    ldmx4(kb4, sbK + (uint32_t)(((ntp * 16 + krow_off) * A_KW
                                                 + 8 * ks + kcol_off) * 4));
                    mma16n8k8(s[2 * ntp],     qf[ks], kb4);
                    mma16n8k8(s[2 * ntp + 1], qf[ks], kb4 + 2);
                }
            }

            // ---- causal mask ----
            const int qr0 = qt * 128 + wrow + gid;
            if (j0 * 64 + 63 > qt * 128 + wrow) {
#pragma unroll
                for (int nt = 0; nt < 8; nt++) {
                    const int c0g = j0 * 64 + nt * 8 + 2 * tig;
                    if (c0g     > qr0)     s[nt][0] = -1e30f;
                    if (c0g + 1 > qr0)     s[nt][1] = -1e30f;
                    if (c0g     > qr0 + 8) s[nt][2] = -1e30f;
                    if (c0g + 1 > qr0 + 8) s[nt][3] = -1e30f;
                }
            }

            // ---- online softmax (exp2 domain, R14 verified) ----
            float mloc0 = -1e30f, mloc1 = -1e30f;
#pragma unroll
            for (int nt = 0; nt < 8; nt++) {
                mloc0 = fmaxf(mloc0, fmaxf(s[nt][0], s[nt][1]));
                mloc1 = fmaxf(mloc1, fmaxf(s[nt][2], s[nt][3]));
            }
            mloc0 = fmaxf(mloc0, __shfl_xor_sync(0xffffffffu, mloc0, 1));
            mloc0 = fmaxf(mloc0, __shfl_xor_sync(0xffffffffu, mloc0, 2));
            mloc1 = fmaxf(mloc1, __shfl_xor_sync(0xffffffffu, mloc1, 1));
            mloc1 = fmaxf(mloc1, __shfl_xor_sync(0xffffffffu, mloc1, 2));

            const float mn0 = fmaxf(m0, mloc0);
            const float mn1 = fmaxf(m1, mloc1);
            const float cr0 = ex2(m0 - mn0);
            const float cr1 = ex2(m1 - mn1);
            m0 = mn0;
            m1 = mn1;

#pragma unroll
            for (int nt = 0; nt < 8; nt++) {
                s[nt][0] = ex2(s[nt][0] - mn0);
                s[nt][1] = ex2(s[nt][1] - mn0);
                s[nt][2] = ex2(s[nt][2] - mn1);
                s[nt][3] = ex2(s[nt][3] - mn1);
                o[nt][0] *= cr0; o[nt][1] *= cr0;
                o[nt][2] *= cr1; o[nt][3] *= cr1;
            }

            // ---- stage P as fp16 (half2 words) ----
#pragma unroll
            for (int nt = 0; nt < 8; nt++) {
                const int wa0 = (wrow + gid) * A_PW + nt * 4 + tig;
                Ps[wa0]              = f2h2(s[nt][0], s[nt][1]);
                Ps[wa0 + 8 * A_PW]   = f2h2(s[nt][2], s[nt][3]);
            }
            __syncwarp();

            // ---- O += P V (fp16 m16n8k16); l via P @ ones ----
            float ls[4] = {0.f, 0.f, 0.f, 0.f};
#pragma unroll
            for (int ks = 0; ks < 4; ks++) {
                uint32_t pa[4];
                ldmx4(pa, sbP + (uint32_t)(((wrow + prow_off) * (A_PW * 2)
                                            + 16 * ks + pcol_off) * 2));
                mma16n8k16h(ls, pa, hones);
#pragma unroll
                for (int ntp = 0; ntp < 4; ntp++) {
                    uint32_t vb4[4];
                    ldmx4(vb4, sbV + (uint32_t)(((ntp * 16 + vrow_off) * (A_VW * 2)
                                                 + 16 * ks + vcol_off) * 2));
                    mma16n8k16h(o[2 * ntp],     pa, vb4);
                    mma16n8k16h(o[2 * ntp + 1], pa, vb4 + 2);
                }
            }
            l0 = l0 * cr0 + ls[0];
            l1 = l1 * cr1 + ls[2];
            __syncwarp();
        }
    }

    // ---- normalize + write tf32 bits ----
    const float inv0 = 1.f / l0;
    const float inv1 = 1.f / l1;
    const int t0 = qt * 128 + wrow + gid;
#pragma unroll
    for (int nt = 0; nt < 8; nt++) {
        const int d = h * HD + nt * 8 + 2 * tig;
        uint2 v0, v1;
        v0.x = f2tf32(o[nt][0] * inv0);
        v0.y = f2tf32(o[nt][1] * inv0);
        v1.x = f2tf32(o[nt][2] * inv1);
        v1.y = f2tf32(o[nt][3] * inv1);
        *(uint2*)&attout[(size_t)(b * SEQ + t0) * C_EMBED + d] = v0;
        *(uint2*)&attout[(size_t)(b * SEQ + t0 + 8) * C_EMBED + d] = v1;
    }
}

// ---------------------------------------------------------------------------
extern "C" void kernel_launch(void* const* d_in, const int* in_sizes, int n_in,
                              void* d_out, int out_size)
{
    const float* x     = (const float*)d_in[0];
    const float* Wqkv  = (const float*)d_in[1];
    const float* bqkv  = (const float*)d_in[2];
    const float* Wproj = (const float*)d_in[3];
    const float* bproj = (const float*)d_in[4];
    float* out = (float*)d_out;

    uint32_t *qkv, *vtp, *att, *xt, *wqkvt, *wprojt;
    cudaGetSymbolAddress((void**)&qkv, g_qkv);
    cudaGetSymbolAddress((void**)&vtp, g_vt);
    cudaGetSymbolAddress((void**)&att, g_att);
    cudaGetSymbolAddress((void**)&xt, g_xt);
    cudaGetSymbolAddress((void**)&wqkvt, g_wqkvt);
    cudaGetSymbolAddress((void**)&wprojt, g_wprojt);

    cudaFuncSetAttribute(gemm_tf32_kernel<0>, cudaFuncAttributeMaxDynamicSharedMemorySize,
                         GEMM_SMEM_BYTES);
    cudaFuncSetAttribute(gemm_tf32_kernel<1>, cudaFuncAttributeMaxDynamicSharedMemorySize,
                         GEMM_SMEM_BYTES);
    cudaFuncSetAttribute(attn_tc_kernel, cudaFuncAttributeMaxDynamicSharedMemorySize,
                         ATTN_SMEM_BYTES);

    // 0) pre-round activations; pre-round + TRANSPOSE weights
    {
        int n4x = (MROWS * C_EMBED) / 4;
        cvt_tf32_kernel<<<(n4x + 255) / 256, 256>>>((const float4*)x, (uint4*)xt, n4x);
        dim3 bt(32, 8);
        dim3 gq(C3 / 32, C_EMBED / 32);
        cvt_transpose_kernel<<<gq, bt>>>(Wqkv, wqkvt, C_EMBED, C3);
        dim3 gp(C_EMBED / 32, C_EMBED / 32);
        cvt_transpose_kernel<<<gp, bt>>>(Wproj, wprojt, C_EMBED, C_EMBED);
    }

    // 1) QKV projection -> Q/K tf32 bits (Q scaled), V fp16 -> g_vt
    dim3 g1(C3 / 128, MROWS / 128);
    gemm_tf32_kernel<1><<<g1, 256, GEMM_SMEM_BYTES>>>(xt, wqkvt, bqkv, (float*)qkv, vtp,
                                                      MROWS, C3, C_EMBED);

    // 2) Causal flash attention -> tf32 bits
    dim3 g2(SEQ / 128, NH, BATCH);
    attn_tc_kernel<<<g2, 256, ATTN_SMEM_BYTES>>>(qkv, vtp, att);

    // 3) Output projection -> fp32
    dim3 g3(C_EMBED / 128, MROWS / 128);
    gemm_tf32_kernel<0><<<g3, 256, GEMM_SMEM_BYTES>>>(att, wprojt, bproj, out, vtp,
                                                      MROWS, C_EMBED, C_EMBED);
}